// round 6
// baseline (speedup 1.0000x reference)
#include <cuda_runtime.h>
#include <math.h>
#include <stdint.h>

#define BB 4
#define CC 64
#define C3 192
#define TT 10
#define HH 64
#define WW 64
#define HW 4096
#define THW 40960
#define HEADS 4
#define CPH 16
#define NN 160
#define DD 4096
#define BH (BB*HEADS)
#define KSPL 8
#define KCH (DD/KSPL)   // 512

// ---------------- scratch (device globals) ---------------------------------
__device__ float g_qkv0[(size_t)BB * C3 * THW];
__device__ float g_qkv1[(size_t)BB * C3 * THW];
__device__ float g_Spart[(size_t)KSPL * BH * NN * NN];
__device__ float g_S[(size_t)BH * NN * NN];
__device__ float g_invq[BH * NN];
__device__ float g_invk[BH * NN];
__device__ float g_O[(size_t)BB * CC * THW];

// ---------------- packed f32x2 helpers --------------------------------------
__device__ __forceinline__ void ffma2(unsigned long long& d,
                                      unsigned long long a, unsigned long long b) {
    asm("fma.rn.f32x2 %0, %1, %2, %0;" : "+l"(d) : "l"(a), "l"(b));
}
__device__ __forceinline__ unsigned long long dup2(float x) {
    unsigned long long r;
    asm("mov.b64 %0, {%1, %1};" : "=l"(r) : "f"(x));
    return r;
}
__device__ __forceinline__ float2 unpk(unsigned long long v) {
    float2 r;
    asm("mov.b64 {%0, %1}, %2;" : "=f"(r.x), "=f"(r.y) : "l"(v));
    return r;
}
__device__ __forceinline__ unsigned long long lds64(const float* p) {
    return *(const unsigned long long*)p;
}
__device__ __forceinline__ uint32_t smem_u32(const void* p) {
    uint32_t a;
    asm("{ .reg .u64 t; cvta.to.shared.u64 t, %1; cvt.u32.u64 %0, t; }" : "=r"(a) : "l"(p));
    return a;
}
__device__ __forceinline__ void cpasync16(uint32_t dst, const void* src) {
    asm volatile("cp.async.cg.shared.global [%0], [%1], 16;" :: "r"(dst), "l"(src));
}
#define CP_COMMIT() asm volatile("cp.async.commit_group;" ::: "memory")
#define CP_WAIT1()  asm volatile("cp.async.wait_group 1;" ::: "memory")
#define CP_WAIT0()  asm volatile("cp.async.wait_group 0;" ::: "memory")

// ---------------- K1 / K7: projection GEMM (FFMA2, multi-CTA/SM) ------------
__global__ __launch_bounds__(128) void gemm_proj2(
    const float* __restrict__ W, const float* __restrict__ X, float* __restrict__ Y,
    long xbstride, long ybstride)
{
    __shared__ __align__(16) float As2[32][132];
    __shared__ __align__(16) float Bs[32][132];
    const int b  = blockIdx.z;
    const int m0 = blockIdx.y * 64;
    const int p0 = blockIdx.x * 128;
    const float* Xb = X + (size_t)b * xbstride;
    float*       Yb = Y + (size_t)b * ybstride;
    const int tid = threadIdx.x;
    const int tm = tid >> 4, tn = tid & 15;

    unsigned long long acc[8][4];
    #pragma unroll
    for (int i = 0; i < 8; i++)
        #pragma unroll
        for (int j = 0; j < 4; j++) acc[i][j] = 0ull;

    for (int kb = 0; kb < 64; kb += 32) {
        #pragma unroll
        for (int j = 0; j < 4; j++) {
            int idx = tid + j * 128;
            int row = idx >> 3;
            int kc  = (idx & 7) * 4;
            float4 w4 = *(const float4*)&W[(size_t)(m0 + row) * 64 + kb + kc];
            *(unsigned long long*)&As2[kc + 0][2 * row] = dup2(w4.x);
            *(unsigned long long*)&As2[kc + 1][2 * row] = dup2(w4.y);
            *(unsigned long long*)&As2[kc + 2][2 * row] = dup2(w4.z);
            *(unsigned long long*)&As2[kc + 3][2 * row] = dup2(w4.w);
        }
        #pragma unroll
        for (int j = 0; j < 8; j++) {
            int idx = tid + j * 128;
            int row = idx >> 5;
            int col = (idx & 31) * 4;
            *(float4*)&Bs[row][col] = *(const float4*)&Xb[(size_t)(kb + row) * THW + p0 + col];
        }
        __syncthreads();
        #pragma unroll 4
        for (int k = 0; k < 32; k++) {
            unsigned long long a[8], bp[4];
            #pragma unroll
            for (int mi = 0; mi < 8; mi++) a[mi] = lds64(&As2[k][2 * (tm * 8 + mi)]);
            #pragma unroll
            for (int u = 0; u < 4; u++)    bp[u] = lds64(&Bs[k][2 * tn + 32 * u]);
            #pragma unroll
            for (int mi = 0; mi < 8; mi++)
                #pragma unroll
                for (int u = 0; u < 4; u++) ffma2(acc[mi][u], a[mi], bp[u]);
        }
        __syncthreads();
    }
    #pragma unroll
    for (int mi = 0; mi < 8; mi++) {
        size_t base = (size_t)(m0 + tm * 8 + mi) * THW + p0 + 2 * tn;
        #pragma unroll
        for (int u = 0; u < 4; u++)
            *(float2*)&Yb[base + 32 * u] = unpk(acc[mi][u]);
    }
}

// ---------------- K2: depthwise 3x3 + temporal mix (fused) ------------------
__global__ __launch_bounds__(256) void dwconv_tmix(
    const float* __restrict__ wdw, const float* __restrict__ wt,
    const float* __restrict__ bt)
{
    __shared__ float tile[TT][18][18];
    const int bc = blockIdx.z;
    const int c  = bc % C3;
    const int h0 = blockIdx.y * 16, w0 = blockIdx.x * 16;
    const float* src = g_qkv0 + (size_t)bc * THW;
    float*       dst = g_qkv1 + (size_t)bc * THW;
    const int tid = threadIdx.x;

    for (int idx = tid; idx < TT * 18 * 18; idx += 256) {
        int t = idx / 324, rem = idx % 324;
        int y = rem / 18, x = rem % 18;
        int gh = h0 + y - 1, gw = w0 + x - 1;
        float v = 0.f;
        if (gh >= 0 && gh < HH && gw >= 0 && gw < WW)
            v = src[(size_t)t * HW + gh * WW + gw];
        tile[t][y][x] = v;
    }
    __syncthreads();

    float wd[9];
    #pragma unroll
    for (int i = 0; i < 9; i++) wd[i] = wdw[c * 9 + i];

    const int y = tid >> 4, x = tid & 15;
    float cv[TT];
    #pragma unroll
    for (int t = 0; t < TT; t++) {
        float s = 0.f;
        #pragma unroll
        for (int kh = 0; kh < 3; kh++)
            #pragma unroll
            for (int kw = 0; kw < 3; kw++)
                s += wd[kh * 3 + kw] * tile[t][y + kh][x + kw];
        cv[t] = s;
    }
    const int hw = (h0 + y) * WW + (w0 + x);
    #pragma unroll
    for (int s = 0; s < TT; s++) {
        float o = bt[s];
        #pragma unroll
        for (int t = 0; t < TT; t++) o += wt[s * TT + t] * cv[t];
        dst[(size_t)s * HW + hw] = o;
    }
}

// ---------------- K3a: L2 norms of q/k rows ---------------------------------
__global__ __launch_bounds__(256) void norms_kernel()
{
    const int warp = (blockIdx.x * 256 + threadIdx.x) >> 5;
    const int lane = threadIdx.x & 31;
    if (warp >= 2 * BH * NN) return;
    const int qk = warp / (BH * NN);
    const int r  = warp % (BH * NN);
    const int bh = r / NN, i = r % NN;
    const int b = bh / HEADS, h = bh % HEADS;
    const float* row = g_qkv1 + ((size_t)b * C3 + qk * CC + h * CPH) * THW + (size_t)i * DD;
    float s = 0.f;
    for (int d = lane * 4; d < DD; d += 128) {
        float4 v = *(const float4*)&row[d];
        s += v.x * v.x + v.y * v.y + v.z * v.z + v.w * v.w;
    }
    #pragma unroll
    for (int off = 16; off; off >>= 1) s += __shfl_xor_sync(0xffffffffu, s, off);
    if (lane == 0) {
        float inv = 1.f / fmaxf(sqrtf(s), 1e-12f);
        (qk ? g_invk : g_invq)[bh * NN + i] = inv;
    }
}

// ---------------- K3b: S partials = Q K^T -----------------------------------
// 512 threads, full 160x160 tile, k-pair FFMA2 (acc.lo = even k, acc.hi = odd),
// cp.async double-buffered, split-K = 8 (128 CTAs, one wave).
#define QKS 36                         // row stride (floats): 144B, 16B-aligned
#define QK_STAGE (2 * 160 * QKS)       // Q block then K block (floats)

__global__ __launch_bounds__(512, 1) void qk_gemm5()
{
    extern __shared__ __align__(16) float sm[];
    const uint32_t sbase = smem_u32(sm);
    const int bh = blockIdx.x;
    const int ks = blockIdx.y;
    const int b = bh >> 2, h = bh & 3;
    const float* Q  = g_qkv1 + ((size_t)b * C3 + h * CPH) * THW + (size_t)ks * KCH;
    const float* Kp = Q + (size_t)CC * THW;
    const int tid = threadIdx.x;
    const int tm = tid >> 5;            // 0..15, warp-uniform
    const int tn = tid & 31;

    // async copy of chunk c (32 k) into stage s
    auto copy_chunk = [&](int c, int s) {
        const int kb = c * 32;
        #pragma unroll
        for (int j = 0; j < 5; j++) {
            int idx = tid + j * 512;            // 0..2559
            int isK = (idx >= 1280);
            int l   = idx - (isK ? 1280 : 0);   // 0..1279
            int row = l >> 3;
            int seg = l & 7;
            const float* src = (isK ? Kp : Q) + (size_t)row * DD + kb + seg * 4;
            uint32_t dst = sbase + (uint32_t)(s * QK_STAGE + isK * 160 * QKS
                                              + row * QKS + seg * 4) * 4u;
            cpasync16(dst, src);
        }
        CP_COMMIT();
    };

    unsigned long long acc[10][5];
    #pragma unroll
    for (int i = 0; i < 10; i++)
        #pragma unroll
        for (int j = 0; j < 5; j++) acc[i][j] = 0ull;

    copy_chunk(0, 0);
    copy_chunk(1, 1);

    for (int c = 0; c < 16; c++) {
        if (c < 15) { CP_WAIT1(); } else { CP_WAIT0(); }
        __syncthreads();
        const float* Qs = sm + (c & 1) * QK_STAGE;
        const float* Ksh = Qs + 160 * QKS;
        #pragma unroll 4
        for (int kp = 0; kp < 16; kp++) {
            unsigned long long bp[5];
            #pragma unroll
            for (int jj = 0; jj < 5; jj++)
                bp[jj] = lds64(&Ksh[(tn + 32 * jj) * QKS + 2 * kp]);
            #pragma unroll
            for (int g = 0; g < 10; g++) {
                unsigned long long a = lds64(&Qs[(tm * 10 + g) * QKS + 2 * kp]);
                #pragma unroll
                for (int jj = 0; jj < 5; jj++) ffma2(acc[g][jj], a, bp[jj]);
            }
        }
        __syncthreads();
        if (c < 14) copy_chunk(c + 2, c & 1);
    }

    float* Sp = g_Spart + ((size_t)ks * BH + bh) * NN * NN;
    #pragma unroll
    for (int g = 0; g < 10; g++) {
        int gi = tm * 10 + g;
        #pragma unroll
        for (int jj = 0; jj < 5; jj++) {
            float2 v = unpk(acc[g][jj]);
            Sp[(size_t)gi * NN + tn + 32 * jj] = v.x + v.y;
        }
    }
}

// ---------------- K3c: reduce split-K + scale + softmax ---------------------
__global__ __launch_bounds__(256) void softmax2(const float* __restrict__ temp)
{
    const int warp = (blockIdx.x * 256 + threadIdx.x) >> 5;
    const int lane = threadIdx.x & 31;
    if (warp >= BH * NN) return;
    const int bh = warp / NN, i = warp % NN;
    const int h = bh & 3;
    const float scale_i = g_invq[bh * NN + i] * temp[h];
    float vals[5];
    float mx = -1e30f;
    #pragma unroll
    for (int j5 = 0; j5 < 5; j5++) {
        int j = lane + j5 * 32;
        float s = 0.f;
        #pragma unroll
        for (int ks = 0; ks < KSPL; ks++)
            s += g_Spart[(((size_t)ks * BH + bh) * NN + i) * NN + j];
        vals[j5] = s * scale_i * g_invk[bh * NN + j];
        mx = fmaxf(mx, vals[j5]);
    }
    #pragma unroll
    for (int off = 16; off; off >>= 1) mx = fmaxf(mx, __shfl_xor_sync(0xffffffffu, mx, off));
    float s = 0.f;
    #pragma unroll
    for (int j5 = 0; j5 < 5; j5++) { vals[j5] = __expf(vals[j5] - mx); s += vals[j5]; }
    #pragma unroll
    for (int off = 16; off; off >>= 1) s += __shfl_xor_sync(0xffffffffu, s, off);
    const float invs = 1.f / s;
    float* row = g_S + (size_t)bh * NN * NN + (size_t)i * NN;
    #pragma unroll
    for (int j5 = 0; j5 < 5; j5++) row[lane + j5 * 32] = vals[j5] * invs;
}

// ---------------- K3d: O = P V ----------------------------------------------
// 256 threads, 2 CTAs/SM, tile 80(i) x 256(d), micro 5x(8x2), cp.async 2-stage.
#define PS 36                          // P row stride (floats)
#define VS 264                         // V row stride (floats)
#define PV_STAGE (80 * PS + 32 * VS)   // floats

__global__ __launch_bounds__(256, 2) void pv_gemm5()
{
    extern __shared__ __align__(16) float sm[];
    const uint32_t sbase = smem_u32(sm);
    const int bh = blockIdx.z;
    const int b = bh >> 2, h = bh & 3;
    const int i0 = blockIdx.y * 80;
    const int d0 = blockIdx.x * 256;
    const float* P = g_S + (size_t)bh * NN * NN;
    const float* V = g_qkv1 + ((size_t)b * C3 + 2 * CC + h * CPH) * THW;
    float*       O = g_O   + ((size_t)b * CC + h * CPH) * THW;
    const int tid = threadIdx.x;
    const int tm = tid >> 4, tn = tid & 15;

    auto copy_chunk = [&](int c, int s) {
        const int kb = c * 32;
        // P: 80 x 32 -> [i][k] rows of PS
        #pragma unroll
        for (int j = 0; j < 3; j++) {
            int idx = tid + j * 256;
            if (idx < 640) {
                int row = idx >> 3, seg = idx & 7;
                cpasync16(sbase + (uint32_t)(s * PV_STAGE + row * PS + seg * 4) * 4u,
                          P + (size_t)(i0 + row) * NN + kb + seg * 4);
            }
        }
        // V: 32 x 256 -> [k][d] rows of VS
        #pragma unroll
        for (int j = 0; j < 8; j++) {
            int idx = tid + j * 256;
            int row = idx >> 6, col = (idx & 63) * 4;
            cpasync16(sbase + (uint32_t)(s * PV_STAGE + 80 * PS + row * VS + col) * 4u,
                      V + (size_t)(kb + row) * DD + d0 + col);
        }
        CP_COMMIT();
    };

    unsigned long long acc[5][8];
    #pragma unroll
    for (int i = 0; i < 5; i++)
        #pragma unroll
        for (int j = 0; j < 8; j++) acc[i][j] = 0ull;

    copy_chunk(0, 0);
    copy_chunk(1, 1);

    for (int c = 0; c < 5; c++) {
        if (c < 4) { CP_WAIT1(); } else { CP_WAIT0(); }
        __syncthreads();
        const float* Ps = sm + (c & 1) * PV_STAGE;
        const float* Vs = Ps + 80 * PS;
        #pragma unroll 4
        for (int k = 0; k < 32; k++) {
            unsigned long long bp[8];
            #pragma unroll
            for (int u = 0; u < 8; u++)
                bp[u] = lds64(&Vs[k * VS + 2 * tn + 32 * u]);
            #pragma unroll
            for (int v = 0; v < 5; v++) {
                unsigned long long a = dup2(Ps[(tm * 5 + v) * PS + k]);
                #pragma unroll
                for (int u = 0; u < 8; u++) ffma2(acc[v][u], a, bp[u]);
            }
        }
        __syncthreads();
        if (c < 3) copy_chunk(c + 2, c & 1);
    }

    #pragma unroll
    for (int v = 0; v < 5; v++) {
        size_t base = (size_t)(i0 + tm * 5 + v) * DD + d0 + 2 * tn;
        #pragma unroll
        for (int u = 0; u < 8; u++)
            *(float2*)&O[base + 32 * u] = unpk(acc[v][u]);
    }
}

// ---------------- host launcher --------------------------------------------
extern "C" void kernel_launch(void* const* d_in, const int* in_sizes, int n_in,
                              void* d_out, int out_size)
{
    const float* x      = (const float*)d_in[0];
    const float* w_qkv  = (const float*)d_in[1];
    const float* w_dw   = (const float*)d_in[2];
    const float* w_t    = (const float*)d_in[3];
    const float* b_t    = (const float*)d_in[4];
    const float* temp   = (const float*)d_in[5];
    const float* w_out  = (const float*)d_in[6];
    float* out = (float*)d_out;

    float *qkv0, *obuf;
    cudaGetSymbolAddress((void**)&qkv0, g_qkv0);
    cudaGetSymbolAddress((void**)&obuf, g_O);

    const int qk_smem = 2 * QK_STAGE * 4;   // 92160 B
    const int pv_smem = 2 * PV_STAGE * 4;   // 90624 B
    cudaFuncSetAttribute(qk_gemm5, cudaFuncAttributeMaxDynamicSharedMemorySize, qk_smem);
    cudaFuncSetAttribute(pv_gemm5, cudaFuncAttributeMaxDynamicSharedMemorySize, pv_smem);

    // K1: qkv projection (192 x 40960 per batch)
    gemm_proj2<<<dim3(THW / 128, C3 / 64, BB), 128>>>(
        w_qkv, x, qkv0, (long)CC * THW, (long)C3 * THW);

    // K2: depthwise 3x3 + temporal mix
    dwconv_tmix<<<dim3(4, 4, BB * C3), 256>>>(w_dw, w_t, b_t);

    // K3a: q/k row norms
    norms_kernel<<<640, 256>>>();

    // K3b: split-K scores (512 threads, k-pair FFMA2, cp.async)
    qk_gemm5<<<dim3(BH, KSPL), 512, qk_smem>>>();

    // K3c: reduce + scale + softmax
    softmax2<<<(BH * NN) / 8, 256>>>(temp);

    // K3d: O = P V (2 CTAs/SM, cp.async)
    pv_gemm5<<<dim3(DD / 256, NN / 80, BH), 256, pv_smem>>>();

    // K7: final projection -> d_out
    gemm_proj2<<<dim3(THW / 128, 1, BB), 128>>>(
        w_out, obuf, out, (long)CC * THW, (long)CC * THW);
}

// round 7
// speedup vs baseline: 1.3647x; 1.3647x over previous
#include <cuda_runtime.h>
#include <math.h>
#include <stdint.h>

#define BB 4
#define CC 64
#define C3 192
#define TT 10
#define HH 64
#define WW 64
#define HW 4096
#define THW 40960
#define HEADS 4
#define CPH 16
#define NN 160
#define DD 4096
#define BH (BB*HEADS)
#define KSPL 8
#define KCH (DD/KSPL)   // 512

// ---------------- scratch (device globals) ---------------------------------
__device__ float g_qkv0[(size_t)BB * C3 * THW];
__device__ float g_qkv1[(size_t)BB * C3 * THW];
__device__ float g_Spart[(size_t)KSPL * BH * NN * NN];
__device__ float g_S[(size_t)BH * NN * NN];
__device__ float g_invq[BH * NN];
__device__ float g_invk[BH * NN];
__device__ float g_O[(size_t)BB * CC * THW];

// ---------------- packed f32x2 helpers --------------------------------------
__device__ __forceinline__ void ffma2(unsigned long long& d,
                                      unsigned long long a, unsigned long long b) {
    asm("fma.rn.f32x2 %0, %1, %2, %0;" : "+l"(d) : "l"(a), "l"(b));
}
__device__ __forceinline__ unsigned long long dup2(float x) {
    unsigned long long r;
    asm("mov.b64 %0, {%1, %1};" : "=l"(r) : "f"(x));
    return r;
}
__device__ __forceinline__ float2 unpk(unsigned long long v) {
    float2 r;
    asm("mov.b64 {%0, %1}, %2;" : "=f"(r.x), "=f"(r.y) : "l"(v));
    return r;
}
__device__ __forceinline__ unsigned long long lds64(const float* p) {
    return *(const unsigned long long*)p;
}
__device__ __forceinline__ uint32_t smem_u32(const void* p) {
    uint32_t a;
    asm("{ .reg .u64 t; cvta.to.shared.u64 t, %1; cvt.u32.u64 %0, t; }" : "=r"(a) : "l"(p));
    return a;
}
__device__ __forceinline__ void cpasync16(uint32_t dst, const void* src) {
    asm volatile("cp.async.cg.shared.global [%0], [%1], 16;" :: "r"(dst), "l"(src));
}
#define CP_COMMIT() asm volatile("cp.async.commit_group;" ::: "memory")
#define CP_WAIT1()  asm volatile("cp.async.wait_group 1;" ::: "memory")
#define CP_WAIT0()  asm volatile("cp.async.wait_group 0;" ::: "memory")

// ---------------- K1 / K7: projection GEMM (FFMA2, multi-CTA/SM) ------------
__global__ __launch_bounds__(128) void gemm_proj2(
    const float* __restrict__ W, const float* __restrict__ X, float* __restrict__ Y,
    long xbstride, long ybstride)
{
    __shared__ __align__(16) float As2[32][132];
    __shared__ __align__(16) float Bs[32][132];
    const int b  = blockIdx.z;
    const int m0 = blockIdx.y * 64;
    const int p0 = blockIdx.x * 128;
    const float* Xb = X + (size_t)b * xbstride;
    float*       Yb = Y + (size_t)b * ybstride;
    const int tid = threadIdx.x;
    const int tm = tid >> 4, tn = tid & 15;

    unsigned long long acc[8][4];
    #pragma unroll
    for (int i = 0; i < 8; i++)
        #pragma unroll
        for (int j = 0; j < 4; j++) acc[i][j] = 0ull;

    for (int kb = 0; kb < 64; kb += 32) {
        #pragma unroll
        for (int j = 0; j < 4; j++) {
            int idx = tid + j * 128;
            int row = idx >> 3;
            int kc  = (idx & 7) * 4;
            float4 w4 = *(const float4*)&W[(size_t)(m0 + row) * 64 + kb + kc];
            *(unsigned long long*)&As2[kc + 0][2 * row] = dup2(w4.x);
            *(unsigned long long*)&As2[kc + 1][2 * row] = dup2(w4.y);
            *(unsigned long long*)&As2[kc + 2][2 * row] = dup2(w4.z);
            *(unsigned long long*)&As2[kc + 3][2 * row] = dup2(w4.w);
        }
        #pragma unroll
        for (int j = 0; j < 8; j++) {
            int idx = tid + j * 128;
            int row = idx >> 5;
            int col = (idx & 31) * 4;
            *(float4*)&Bs[row][col] = *(const float4*)&Xb[(size_t)(kb + row) * THW + p0 + col];
        }
        __syncthreads();
        #pragma unroll 4
        for (int k = 0; k < 32; k++) {
            unsigned long long a[8], bp[4];
            #pragma unroll
            for (int mi = 0; mi < 8; mi++) a[mi] = lds64(&As2[k][2 * (tm * 8 + mi)]);
            #pragma unroll
            for (int u = 0; u < 4; u++)    bp[u] = lds64(&Bs[k][2 * tn + 32 * u]);
            #pragma unroll
            for (int mi = 0; mi < 8; mi++)
                #pragma unroll
                for (int u = 0; u < 4; u++) ffma2(acc[mi][u], a[mi], bp[u]);
        }
        __syncthreads();
    }
    #pragma unroll
    for (int mi = 0; mi < 8; mi++) {
        size_t base = (size_t)(m0 + tm * 8 + mi) * THW + p0 + 2 * tn;
        #pragma unroll
        for (int u = 0; u < 4; u++)
            *(float2*)&Yb[base + 32 * u] = unpk(acc[mi][u]);
    }
}

// ---------------- K2: depthwise 3x3 + temporal mix (fused) ------------------
__global__ __launch_bounds__(256) void dwconv_tmix(
    const float* __restrict__ wdw, const float* __restrict__ wt,
    const float* __restrict__ bt)
{
    __shared__ float tile[TT][18][18];
    const int bc = blockIdx.z;
    const int c  = bc % C3;
    const int h0 = blockIdx.y * 16, w0 = blockIdx.x * 16;
    const float* src = g_qkv0 + (size_t)bc * THW;
    float*       dst = g_qkv1 + (size_t)bc * THW;
    const int tid = threadIdx.x;

    for (int idx = tid; idx < TT * 18 * 18; idx += 256) {
        int t = idx / 324, rem = idx % 324;
        int y = rem / 18, x = rem % 18;
        int gh = h0 + y - 1, gw = w0 + x - 1;
        float v = 0.f;
        if (gh >= 0 && gh < HH && gw >= 0 && gw < WW)
            v = src[(size_t)t * HW + gh * WW + gw];
        tile[t][y][x] = v;
    }
    __syncthreads();

    float wd[9];
    #pragma unroll
    for (int i = 0; i < 9; i++) wd[i] = wdw[c * 9 + i];

    const int y = tid >> 4, x = tid & 15;
    float cv[TT];
    #pragma unroll
    for (int t = 0; t < TT; t++) {
        float s = 0.f;
        #pragma unroll
        for (int kh = 0; kh < 3; kh++)
            #pragma unroll
            for (int kw = 0; kw < 3; kw++)
                s += wd[kh * 3 + kw] * tile[t][y + kh][x + kw];
        cv[t] = s;
    }
    const int hw = (h0 + y) * WW + (w0 + x);
    #pragma unroll
    for (int s = 0; s < TT; s++) {
        float o = bt[s];
        #pragma unroll
        for (int t = 0; t < TT; t++) o += wt[s * TT + t] * cv[t];
        dst[(size_t)s * HW + hw] = o;
    }
}

// ---------------- K3a: L2 norms of q/k rows ---------------------------------
__global__ __launch_bounds__(256) void norms_kernel()
{
    const int warp = (blockIdx.x * 256 + threadIdx.x) >> 5;
    const int lane = threadIdx.x & 31;
    if (warp >= 2 * BH * NN) return;
    const int qk = warp / (BH * NN);
    const int r  = warp % (BH * NN);
    const int bh = r / NN, i = r % NN;
    const int b = bh / HEADS, h = bh % HEADS;
    const float* row = g_qkv1 + ((size_t)b * C3 + qk * CC + h * CPH) * THW + (size_t)i * DD;
    float s = 0.f;
    for (int d = lane * 4; d < DD; d += 128) {
        float4 v = *(const float4*)&row[d];
        s += v.x * v.x + v.y * v.y + v.z * v.z + v.w * v.w;
    }
    #pragma unroll
    for (int off = 16; off; off >>= 1) s += __shfl_xor_sync(0xffffffffu, s, off);
    if (lane == 0) {
        float inv = 1.f / fmaxf(sqrtf(s), 1e-12f);
        (qk ? g_invk : g_invq)[bh * NN + i] = inv;
    }
}

// ---------------- K3b: S partials = Q K^T -----------------------------------
// 512 threads (4 warps/SMSP), 160x160 tile, micro 5x(5x2) FFMA2, dup-A smem,
// register-prefetch double buffering, split-K = 8.
#define QAS 330                        // dup-A row stride (floats), 2-way banks
#define QBS 166                        // K row stride (floats)
#define QK_STG (32 * QAS + 32 * QBS)   // one stage, floats

__global__ __launch_bounds__(512, 1) void qk_gemm6()
{
    extern __shared__ __align__(16) float sm[];
    const int bh = blockIdx.x;
    const int ks = blockIdx.y;
    const int b = bh >> 2, h = bh & 3;
    const float* Q  = g_qkv1 + ((size_t)b * C3 + h * CPH) * THW + (size_t)ks * KCH;
    const float* Kp = Q + (size_t)CC * THW;
    const int tid = threadIdx.x;
    const int tm = tid >> 4;            // 0..31 -> rows tm*5..tm*5+4
    const int tn = tid & 15;            // 0..15 -> col pairs 10tn..10tn+9

    // per-thread load coords: 5 float4 segments over Q(1280) then K(1280)
    int lisK[5], lrow[5], lseg[5];
    #pragma unroll
    for (int j = 0; j < 5; j++) {
        int idx = tid + j * 512;        // 0..2559
        lisK[j] = idx >= 1280;
        int l = idx - lisK[j] * 1280;
        lrow[j] = l >> 3;
        lseg[j] = (l & 7) * 4;
    }

    unsigned long long acc[5][5];
    #pragma unroll
    for (int i = 0; i < 5; i++)
        #pragma unroll
        for (int j = 0; j < 5; j++) acc[i][j] = 0ull;

    float4 r[5];
    auto gload = [&](int c) {
        const int kb = c * 32;
        #pragma unroll
        for (int j = 0; j < 5; j++)
            r[j] = *(const float4*)((lisK[j] ? Kp : Q) + (size_t)lrow[j] * DD + kb + lseg[j]);
    };
    auto sstore = [&](int s) {
        float* Qs2 = sm + s * QK_STG;
        float* Ksh = Qs2 + 32 * QAS;
        #pragma unroll
        for (int j = 0; j < 5; j++) {
            if (lisK[j]) {
                Ksh[(lseg[j] + 0) * QBS + lrow[j]] = r[j].x;
                Ksh[(lseg[j] + 1) * QBS + lrow[j]] = r[j].y;
                Ksh[(lseg[j] + 2) * QBS + lrow[j]] = r[j].z;
                Ksh[(lseg[j] + 3) * QBS + lrow[j]] = r[j].w;
            } else {
                *(unsigned long long*)&Qs2[(lseg[j] + 0) * QAS + 2 * lrow[j]] = dup2(r[j].x);
                *(unsigned long long*)&Qs2[(lseg[j] + 1) * QAS + 2 * lrow[j]] = dup2(r[j].y);
                *(unsigned long long*)&Qs2[(lseg[j] + 2) * QAS + 2 * lrow[j]] = dup2(r[j].z);
                *(unsigned long long*)&Qs2[(lseg[j] + 3) * QAS + 2 * lrow[j]] = dup2(r[j].w);
            }
        }
    };

    gload(0);
    sstore(0);
    __syncthreads();

    for (int c = 0; c < 16; c++) {
        if (c < 15) gload(c + 1);
        const float* Qs2 = sm + (c & 1) * QK_STG;
        const float* Ksh = Qs2 + 32 * QAS;
        #pragma unroll 4
        for (int k = 0; k < 32; k++) {
            unsigned long long a[5], bp[5];
            #pragma unroll
            for (int g = 0; g < 5; g++) a[g]  = lds64(&Qs2[k * QAS + 10 * tm + 2 * g]);
            #pragma unroll
            for (int u = 0; u < 5; u++) bp[u] = lds64(&Ksh[k * QBS + 10 * tn + 2 * u]);
            #pragma unroll
            for (int g = 0; g < 5; g++)
                #pragma unroll
                for (int u = 0; u < 5; u++) ffma2(acc[g][u], a[g], bp[u]);
        }
        if (c < 15) sstore((c + 1) & 1);
        __syncthreads();
    }

    float* Sp = g_Spart + ((size_t)ks * BH + bh) * NN * NN;
    #pragma unroll
    for (int g = 0; g < 5; g++) {
        int gi = tm * 5 + g;
        #pragma unroll
        for (int u = 0; u < 5; u++)
            *(float2*)&Sp[(size_t)gi * NN + 10 * tn + 2 * u] = unpk(acc[g][u]);
    }
}

// ---------------- K3c: reduce split-K + scale + softmax ---------------------
__global__ __launch_bounds__(256) void softmax2(const float* __restrict__ temp)
{
    const int warp = (blockIdx.x * 256 + threadIdx.x) >> 5;
    const int lane = threadIdx.x & 31;
    if (warp >= BH * NN) return;
    const int bh = warp / NN, i = warp % NN;
    const int h = bh & 3;
    const float scale_i = g_invq[bh * NN + i] * temp[h];
    float vals[5];
    float mx = -1e30f;
    #pragma unroll
    for (int j5 = 0; j5 < 5; j5++) {
        int j = lane + j5 * 32;
        float s = 0.f;
        #pragma unroll
        for (int ks = 0; ks < KSPL; ks++)
            s += g_Spart[(((size_t)ks * BH + bh) * NN + i) * NN + j];
        vals[j5] = s * scale_i * g_invk[bh * NN + j];
        mx = fmaxf(mx, vals[j5]);
    }
    #pragma unroll
    for (int off = 16; off; off >>= 1) mx = fmaxf(mx, __shfl_xor_sync(0xffffffffu, mx, off));
    float s = 0.f;
    #pragma unroll
    for (int j5 = 0; j5 < 5; j5++) { vals[j5] = __expf(vals[j5] - mx); s += vals[j5]; }
    #pragma unroll
    for (int off = 16; off; off >>= 1) s += __shfl_xor_sync(0xffffffffu, s, off);
    const float invs = 1.f / s;
    float* row = g_S + (size_t)bh * NN * NN + (size_t)i * NN;
    #pragma unroll
    for (int j5 = 0; j5 < 5; j5++) row[lane + j5 * 32] = vals[j5] * invs;
}

// ---------------- K3d: O = P V ----------------------------------------------
// 256 threads, 2 CTAs/SM, tile 80(i) x 256(d), micro 5x(8x2), cp.async 2-stage.
#define PS 36                          // P row stride (floats)
#define VS 264                         // V row stride (floats)
#define PV_STAGE (80 * PS + 32 * VS)   // floats

__global__ __launch_bounds__(256, 2) void pv_gemm5()
{
    extern __shared__ __align__(16) float sm[];
    const uint32_t sbase = smem_u32(sm);
    const int bh = blockIdx.z;
    const int b = bh >> 2, h = bh & 3;
    const int i0 = blockIdx.y * 80;
    const int d0 = blockIdx.x * 256;
    const float* P = g_S + (size_t)bh * NN * NN;
    const float* V = g_qkv1 + ((size_t)b * C3 + 2 * CC + h * CPH) * THW;
    float*       O = g_O   + ((size_t)b * CC + h * CPH) * THW;
    const int tid = threadIdx.x;
    const int tm = tid >> 4, tn = tid & 15;

    auto copy_chunk = [&](int c, int s) {
        const int kb = c * 32;
        #pragma unroll
        for (int j = 0; j < 3; j++) {
            int idx = tid + j * 256;
            if (idx < 640) {
                int row = idx >> 3, seg = idx & 7;
                cpasync16(sbase + (uint32_t)(s * PV_STAGE + row * PS + seg * 4) * 4u,
                          P + (size_t)(i0 + row) * NN + kb + seg * 4);
            }
        }
        #pragma unroll
        for (int j = 0; j < 8; j++) {
            int idx = tid + j * 256;
            int row = idx >> 6, col = (idx & 63) * 4;
            cpasync16(sbase + (uint32_t)(s * PV_STAGE + 80 * PS + row * VS + col) * 4u,
                      V + (size_t)(kb + row) * DD + d0 + col);
        }
        CP_COMMIT();
    };

    unsigned long long acc[5][8];
    #pragma unroll
    for (int i = 0; i < 5; i++)
        #pragma unroll
        for (int j = 0; j < 8; j++) acc[i][j] = 0ull;

    copy_chunk(0, 0);
    copy_chunk(1, 1);

    for (int c = 0; c < 5; c++) {
        if (c < 4) { CP_WAIT1(); } else { CP_WAIT0(); }
        __syncthreads();
        const float* Ps = sm + (c & 1) * PV_STAGE;
        const float* Vs = Ps + 80 * PS;
        #pragma unroll 4
        for (int k = 0; k < 32; k++) {
            unsigned long long bp[8];
            #pragma unroll
            for (int u = 0; u < 8; u++)
                bp[u] = lds64(&Vs[k * VS + 2 * tn + 32 * u]);
            #pragma unroll
            for (int v = 0; v < 5; v++) {
                unsigned long long a = dup2(Ps[(tm * 5 + v) * PS + k]);
                #pragma unroll
                for (int u = 0; u < 8; u++) ffma2(acc[v][u], a, bp[u]);
            }
        }
        __syncthreads();
        if (c < 3) copy_chunk(c + 2, c & 1);
    }

    #pragma unroll
    for (int v = 0; v < 5; v++) {
        size_t base = (size_t)(i0 + tm * 5 + v) * DD + d0 + 2 * tn;
        #pragma unroll
        for (int u = 0; u < 8; u++)
            *(float2*)&O[base + 32 * u] = unpk(acc[v][u]);
    }
}

// ---------------- host launcher --------------------------------------------
extern "C" void kernel_launch(void* const* d_in, const int* in_sizes, int n_in,
                              void* d_out, int out_size)
{
    const float* x      = (const float*)d_in[0];
    const float* w_qkv  = (const float*)d_in[1];
    const float* w_dw   = (const float*)d_in[2];
    const float* w_t    = (const float*)d_in[3];
    const float* b_t    = (const float*)d_in[4];
    const float* temp   = (const float*)d_in[5];
    const float* w_out  = (const float*)d_in[6];
    float* out = (float*)d_out;

    float *qkv0, *obuf;
    cudaGetSymbolAddress((void**)&qkv0, g_qkv0);
    cudaGetSymbolAddress((void**)&obuf, g_O);

    const int qk_smem = 2 * QK_STG * 4;     // 126976 B
    const int pv_smem = 2 * PV_STAGE * 4;   // 90624 B
    cudaFuncSetAttribute(qk_gemm6, cudaFuncAttributeMaxDynamicSharedMemorySize, qk_smem);
    cudaFuncSetAttribute(pv_gemm5, cudaFuncAttributeMaxDynamicSharedMemorySize, pv_smem);

    // K1: qkv projection (192 x 40960 per batch)
    gemm_proj2<<<dim3(THW / 128, C3 / 64, BB), 128>>>(
        w_qkv, x, qkv0, (long)CC * THW, (long)C3 * THW);

    // K2: depthwise 3x3 + temporal mix
    dwconv_tmix<<<dim3(4, 4, BB * C3), 256>>>(w_dw, w_t, b_t);

    // K3a: q/k row norms
    norms_kernel<<<640, 256>>>();

    // K3b: split-K scores (512 threads, 4 warps/SMSP)
    qk_gemm6<<<dim3(BH, KSPL), 512, qk_smem>>>();

    // K3c: reduce + scale + softmax
    softmax2<<<(BH * NN) / 8, 256>>>(temp);

    // K3d: O = P V (2 CTAs/SM, cp.async)
    pv_gemm5<<<dim3(DD / 256, NN / 80, BH), 256, pv_smem>>>();

    // K7: final projection -> d_out
    gemm_proj2<<<dim3(THW / 128, 1, BB), 128>>>(
        w_out, obuf, out, (long)CC * THW, (long)CC * THW);
}